// round 12
// baseline (speedup 1.0000x reference)
#include <cuda_runtime.h>
#include <cuda_fp16.h>
#include <cstdint>

#define NDIM 512
#define DDIM 128
#define NN (NDIM*NDIM)

// ---------------- scratch (device globals; no allocation allowed) ----------------
// packed fp16 tensors: each uint32 = (lo16<<16)|hi16 along fake-k axis
__device__ __align__(256) uint32_t g_lP[(size_t)DDIM*NN];   // left, dup-packed
__device__ __align__(256) uint32_t g_rP[(size_t)DDIM*NN];   // right, split-packed
__device__ __align__(256) __half g_gate[(size_t)NN*DDIM];   // fp16 gate
__device__ __align__(256) __half g_accT[(size_t)DDIM*NN];   // fp16 [d][i][j]
// pre-packed weights (dup fp16): 0=lp 1=lg 2=rp 3=rg 4=og 5=op
__device__ __align__(256) uint32_t g_wp[6*16384];

__device__ __forceinline__ float sigf(float x){ return 1.0f/(1.0f+__expf(-x)); }

__device__ __forceinline__ uint32_t pk_split(float v){
    __half h = __float2half_rn(v);
    __half l = __float2half_rn(v - __half2float(h));
    return (uint32_t)__half_as_ushort(h) | ((uint32_t)__half_as_ushort(l) << 16);
}
__device__ __forceinline__ uint32_t pk_dup(float v){
    uint32_t h = (uint32_t)__half_as_ushort(__float2half_rn(v));
    return h | (h << 16);
}

__device__ __forceinline__ uint32_t smem_u32(const void* p){
    uint32_t a;
    asm("{ .reg .u64 t; cvta.to.shared.u64 t, %1; cvt.u32.u64 %0, t; }" : "=r"(a) : "l"(p));
    return a;
}

// ---------------- baseline-PTX tensor-core helpers (fp16) ----------------
__device__ __forceinline__ void ldsm4(uint32_t (&r)[4], uint32_t a){
    asm volatile("ldmatrix.sync.aligned.m8n8.x4.shared.b16 {%0,%1,%2,%3}, [%4];"
        : "=r"(r[0]), "=r"(r[1]), "=r"(r[2]), "=r"(r[3]) : "r"(a));
}
__device__ __forceinline__ void ldsm2(uint32_t (&r)[2], uint32_t a){
    asm volatile("ldmatrix.sync.aligned.m8n8.x2.shared.b16 {%0,%1}, [%2];"
        : "=r"(r[0]), "=r"(r[1]) : "r"(a));
}
__device__ __forceinline__ void mma_f16(float (&c)[4], const uint32_t (&a)[4], const uint32_t (&b)[2]){
    asm volatile("mma.sync.aligned.m16n8k16.row.col.f32.f16.f16.f32 "
        "{%0,%1,%2,%3}, {%4,%5,%6,%7}, {%8,%9}, {%0,%1,%2,%3};"
        : "+f"(c[0]), "+f"(c[1]), "+f"(c[2]), "+f"(c[3])
        : "r"(a[0]), "r"(a[1]), "r"(a[2]), "r"(a[3]), "r"(b[0]), "r"(b[1]));
}
#define CP_ASYNC16(dst, src) \
    asm volatile("cp.async.cg.shared.global [%0], [%1], 16;" :: "r"(dst), "l"(src) : "memory")
#define CP_COMMIT() asm volatile("cp.async.commit_group;" ::: "memory")
#define CP_WAIT0()  asm volatile("cp.async.wait_group 0;" ::: "memory")
#define CP_WAIT1()  asm volatile("cp.async.wait_group 1;" ::: "memory")
#define CP_WAIT2()  asm volatile("cp.async.wait_group 2;" ::: "memory")

// ---------------- Kernel 0: pre-pack weights (dup fp16) ----------------
__global__ void k0_prep(const float* __restrict__ lpw, const float* __restrict__ lgw,
                        const float* __restrict__ rpw, const float* __restrict__ rgw,
                        const float* __restrict__ ogw, const float* __restrict__ opw)
{
    const float* srcs[6] = {lpw, lgw, rpw, rgw, ogw, opw};
    int m = blockIdx.y;
    int idx = blockIdx.x * 256 + threadIdx.x;
    g_wp[m*16384 + idx] = pk_dup(srcs[m][idx]);
}

// ================= Kernel 1: LN + 5 gated projections (64-row tiles, 2 CTA/SM) ==========
// smem: A packed [0,32K) 64 rows x 512B ; W packed [32K,96K) 128 rows x 512B
//       st (uint32 staging) overlays the W region
__global__ void __launch_bounds__(256, 2)
k1_tc(const float* __restrict__ pair, const float* __restrict__ mask,
      const float* __restrict__ nw,  const float* __restrict__ nb,
      const float* __restrict__ lpb, const float* __restrict__ lgb,
      const float* __restrict__ rpb, const float* __restrict__ rgb,
      const float* __restrict__ ogb)
{
    extern __shared__ char smraw[];
    char* smb = (char*)(((uintptr_t)smraw + 1023) & ~(uintptr_t)1023);
    const uint32_t sb = smem_u32(smb);
    uint32_t* st = (uint32_t*)(smb + 32768);
    __shared__ float mask_s[64];
    __shared__ float pb_s[128], gb_s[128];

    const int tid  = threadIdx.x;
    const int lane = tid & 31;
    const int wid  = tid >> 5;
    const int wm   = wid & 1;
    const int wn   = wid >> 1;
    const int row0 = blockIdx.x * 64;
    const int i_idx = row0 >> 9;
    const int k0    = row0 & 511;

    auto loadW = [&](const uint32_t* src){
        #pragma unroll
        for (int t = 0; t < 16; t++){
            int idx = tid + (t << 8);          // 0..4095 16B chunks
            int d = idx >> 5;
            int c = idx & 31;
            uint32_t off = (uint32_t)(d*512 + (((c ^ (d & 7)) << 4)));
            CP_ASYNC16(sb + 32768 + off, (const char*)src + (idx << 4));
        }
        CP_COMMIT();
    };

    // prefetch first weight (lp) — overlapped with LN below
    loadW(g_wp);
    if (tid < 64) mask_s[tid] = mask[row0 + tid];

    // ---- LN from registers (4 threads per row), write packed-split A ----
    {
        int row = tid >> 2, q = tid & 3;
        const float4* pr = (const float4*)(pair + (size_t)(row0 + row)*128 + q*32);
        float v[32];
        float s = 0.f, ss = 0.f;
        #pragma unroll
        for (int t = 0; t < 8; t++){
            float4 x = pr[t];
            v[t*4+0] = x.x; v[t*4+1] = x.y; v[t*4+2] = x.z; v[t*4+3] = x.w;
            s  += x.x + x.y + x.z + x.w;
            ss += x.x*x.x + x.y*x.y + x.z*x.z + x.w*x.w;
        }
        s  += __shfl_xor_sync(0xFFFFFFFFu, s, 1);
        ss += __shfl_xor_sync(0xFFFFFFFFu, ss, 1);
        s  += __shfl_xor_sync(0xFFFFFFFFu, s, 2);
        ss += __shfl_xor_sync(0xFFFFFFFFu, ss, 2);
        float m  = s * (1.f/128.f);
        float vv = fmaxf(ss * (1.f/128.f) - m*m, 0.f);
        float iv = rsqrtf(vv + 1e-5f);
        #pragma unroll
        for (int cc = 0; cc < 8; cc++){
            int c = q*8 + cc;
            int e = q*32 + cc*4;
            uint4 pv;
            uint32_t* pp = (uint32_t*)&pv;
            #pragma unroll
            for (int t = 0; t < 4; t++){
                float y = (v[cc*4 + t] - m)*iv*nw[e + t] + nb[e + t];
                pp[t] = pk_split(y);
            }
            uint32_t off = (uint32_t)(row*512 + (((c ^ (row & 7)) << 4)));
            *(uint4*)(smb + off) = pv;
        }
    }

    // GEMM: A packed [0,32K), W packed [32K,96K). 1 MMA per (fkk,mt,nt).
    auto gemmW = [&](float (&acc)[2][4][4]){
        #pragma unroll
        for (int a = 0; a < 2; a++)
            #pragma unroll
            for (int b = 0; b < 4; b++)
                #pragma unroll
                for (int q = 0; q < 4; q++) acc[a][b][q] = 0.f;
        #pragma unroll 1
        for (int fkk = 0; fkk < 16; fkk++){
            uint32_t ap[2][4];
            #pragma unroll
            for (int mt = 0; mt < 2; mt++){
                int r = wm*32 + mt*16 + (lane & 15);
                int c = fkk*2 + (lane >> 4);
                ldsm4(ap[mt], sb + (uint32_t)(r*512 + (((c ^ (r & 7)) << 4))));
            }
            uint32_t bp[4][2];
            #pragma unroll
            for (int nt = 0; nt < 4; nt++){
                int l = lane & 15;
                int n = wn*32 + nt*8 + (l & 7);
                int c = fkk*2 + (l >> 3);
                ldsm2(bp[nt], sb + 32768 + (uint32_t)(n*512 + (((c ^ (n & 7)) << 4))));
            }
            #pragma unroll
            for (int mt = 0; mt < 2; mt++)
                #pragma unroll
                for (int nt = 0; nt < 4; nt++)
                    mma_f16(acc[mt][nt], ap[mt], bp[nt]);
        }
    };

    // ---- passes A (left, dup-packed out) / B (right, split-packed out) ----
    #pragma unroll 1
    for (int pa = 0; pa < 2; pa++){
        if (pa) loadW(g_wp + 2*16384);
        if (tid < 128){
            pb_s[tid] = pa ? rpb[tid] : lpb[tid];
            gb_s[tid] = pa ? rgb[tid] : lgb[tid];
        }
        CP_WAIT0();
        __syncthreads();
        float accp[2][4][4];
        gemmW(accp);
        __syncthreads();

        loadW(g_wp + (pa*2+1)*16384);
        CP_WAIT0();
        __syncthreads();
        float accg[2][4][4];
        gemmW(accg);
        __syncthreads();

        #pragma unroll
        for (int mt = 0; mt < 2; mt++)
            #pragma unroll
            for (int nt = 0; nt < 4; nt++)
                #pragma unroll
                for (int q = 0; q < 4; q++){
                    int m = wm*32 + mt*16 + (lane >> 2) + ((q >> 1) << 3);
                    int n = wn*32 + nt*8 + ((lane & 3) << 1) + (q & 1);
                    float x = accp[mt][nt][q] + pb_s[n];
                    float g = accg[mt][nt][q] + gb_s[n];
                    float y = x * sigf(g) * mask_s[m];
                    st[m*129 + n] = pa ? pk_split(y) : pk_dup(y);
                }
        __syncthreads();

        // transpose write: packed [d][i][k]
        {
            uint32_t* gP = pa ? g_rP : g_lP;
            int dd = tid >> 1, half = tid & 1;
            uint4 o[8];
            uint32_t* op = (uint32_t*)o;
            #pragma unroll
            for (int kk = 0; kk < 32; kk++)
                op[kk] = st[(half*32 + kk)*129 + dd];
            uint32_t* dst = gP + ((size_t)dd*NDIM + i_idx)*NDIM + k0 + half*32;
            #pragma unroll
            for (int q = 0; q < 8; q++)
                *(uint4*)(dst + q*4) = o[q];
        }
        __syncthreads();
    }

    // ---- pass C: output gate (direct fp16 stores) ----
    loadW(g_wp + 4*16384);
    if (tid < 128) pb_s[tid] = ogb[tid];
    CP_WAIT0();
    __syncthreads();
    {
        float acc[2][4][4];
        gemmW(acc);
        #pragma unroll
        for (int mt = 0; mt < 2; mt++)
            #pragma unroll
            for (int nt = 0; nt < 4; nt++)
                #pragma unroll
                for (int qq = 0; qq < 2; qq++){
                    int m = wm*32 + mt*16 + (lane >> 2) + qq*8;
                    int n = wn*32 + nt*8 + ((lane & 3) << 1);
                    float gx = sigf(acc[mt][nt][qq*2+0] + pb_s[n+0]);
                    float gy = sigf(acc[mt][nt][qq*2+1] + pb_s[n+1]);
                    *(__half2*)&g_gate[(size_t)(row0 + m)*DDIM + n] = __floats2half2_rn(gx, gy);
                }
    }
}

// ================= Kernel 2: einsum, 128x64 tiles, K32 chunks, 3-stage, 3 CTA/SM =========
// per buffer (24KB): A packed [0,16K) 128x128B ; B packed [16K,24K) 64x128B
#define K2_BUF 24576

__global__ void __launch_bounds__(256, 3)
k2_mma()
{
    extern __shared__ char smraw[];
    char* smb = (char*)(((uintptr_t)smraw + 127) & ~(uintptr_t)127);
    const uint32_t sb = smem_u32(smb);

    const int tid  = threadIdx.x;
    const int lane = tid & 31;
    const int wid  = tid >> 5;
    const int d    = blockIdx.y;
    const int i0   = (blockIdx.x >> 3) * 128;
    const int j0   = (blockIdx.x & 7) * 64;
    const int wm   = wid & 3;          // 4 m-groups of 32 rows
    const int wn   = wid >> 2;         // 2 n-groups of 32 cols

    auto load_chunk = [&](int kc, int b){
        #pragma unroll
        for (int t = 0; t < 6; t++){
            int idx = tid + (t << 8);          // 0..1535 16B chunks
            const uint32_t* src;
            int rb, r;
            uint32_t roff;
            if (idx < 1024){
                src = g_lP; rb = i0; r = idx >> 3; roff = 0u;
            } else {
                int x = idx - 1024;
                src = g_rP; rb = j0; r = x >> 3; roff = 16384u;
            }
            int c = idx & 7;
            const void* gp = src + ((size_t)d*NDIM + rb + r)*NDIM + kc + (c << 2);
            uint32_t dst = sb + b*K2_BUF + roff + (r << 7) + (((c ^ (r & 7)) << 4));
            CP_ASYNC16(dst, gp);
        }
        CP_COMMIT();
    };

    float acc[2][4][4];
    #pragma unroll
    for (int a = 0; a < 2; a++)
        #pragma unroll
        for (int b = 0; b < 4; b++)
            #pragma unroll
            for (int q = 0; q < 4; q++) acc[a][b][q] = 0.f;

    load_chunk(0, 0);
    load_chunk(32, 1);
    load_chunk(64, 2);

    int cs = 0;
    #pragma unroll 1
    for (int t = 0; t < 16; t++){
        if (t <= 13)      CP_WAIT2();
        else if (t == 14) CP_WAIT1();
        else              CP_WAIT0();
        __syncthreads();

        const uint32_t base = sb + cs*K2_BUF;
        #pragma unroll
        for (int fkk = 0; fkk < 4; fkk++){
            uint32_t ap[2][4], bp[4][2];
            #pragma unroll
            for (int mt = 0; mt < 2; mt++){
                int m = wm*32 + mt*16 + (lane & 15);
                int c = fkk*2 + (lane >> 4);
                ldsm4(ap[mt], base + (uint32_t)((m << 7) + (((c ^ (m & 7)) << 4))));
            }
            #pragma unroll
            for (int nt = 0; nt < 4; nt++){
                int l = lane & 15;
                int n = wn*32 + nt*8 + (l & 7);
                int c = fkk*2 + (l >> 3);
                ldsm2(bp[nt], base + 16384 + (uint32_t)((n << 7) + (((c ^ (n & 7)) << 4))));
            }
            #pragma unroll
            for (int mt = 0; mt < 2; mt++)
                #pragma unroll
                for (int nt = 0; nt < 4; nt++)
                    mma_f16(acc[mt][nt], ap[mt], bp[nt]);
        }
        __syncthreads();
        if (t + 3 < 16) load_chunk((t + 3)*32, cs);   // cs buffer just freed
        cs = (cs == 2) ? 0 : cs + 1;
    }

    // epilogue: write accT fp16 (half2 along j)
    #pragma unroll
    for (int mt = 0; mt < 2; mt++){
        int r0 = i0 + wm*32 + mt*16 + (lane >> 2);
        #pragma unroll
        for (int nt = 0; nt < 4; nt++){
            int c0 = j0 + wn*32 + nt*8 + (lane & 3)*2;
            __half* p0 = &g_accT[((size_t)d*NDIM + r0)*NDIM + c0];
            __half* p1 = &g_accT[((size_t)d*NDIM + r0 + 8)*NDIM + c0];
            *(__half2*)p0 = __floats2half2_rn(acc[mt][nt][0], acc[mt][nt][1]);
            *(__half2*)p1 = __floats2half2_rn(acc[mt][nt][2], acc[mt][nt][3]);
        }
    }
}

// ================= Kernel 3: LN(accT) @ opw.T + opb, times gate (64-j tiles, 2 CTA/SM) ====
// smem: A packed [0,32K) (accT staging ts overlays [0,16K) before pack phase)
//       W packed [32K,96K) (prefetched, separate cp.async group)
__global__ void __launch_bounds__(256, 2)
k3_tc(const float* __restrict__ onw, const float* __restrict__ onb,
      const float* __restrict__ opb, float* __restrict__ out)
{
    extern __shared__ char smraw[];
    char* smb = (char*)(((uintptr_t)smraw + 1023) & ~(uintptr_t)1023);
    const uint32_t sb = smem_u32(smb);
    __shared__ float pb_s[128];
    __shared__ float sred[4][64], qred[4][64];
    __shared__ float mean_s[64], inv_s[64];

    const int tid  = threadIdx.x;
    const int lane = tid & 31;
    const int wid  = tid >> 5;
    const int wm   = wid & 1;
    const int wn   = wid >> 1;
    const int i_idx = blockIdx.x >> 3;
    const int j0    = (blockIdx.x & 7) * 64;
    const int row0  = i_idx*NDIM + j0;

    // group 0: accT tile -> ts (overlays A region [0,16K)), fully coalesced
    #pragma unroll
    for (int t = 0; t < 4; t++){
        int idx = tid + (t << 8);          // 0..1023 16B chunks
        int d = idx >> 3;                  // row = d (128 rows x 128B)
        int c = idx & 7;
        CP_ASYNC16(sb + (uint32_t)(d*128 + c*16),
                   (const char*)(g_accT + (size_t)d*NN + row0) + c*16);
    }
    CP_COMMIT();

    // group 1: op weight prefetch
    #pragma unroll
    for (int t = 0; t < 16; t++){
        int idx = tid + (t << 8);
        int d = idx >> 5;
        int c = idx & 31;
        uint32_t off = (uint32_t)(d*512 + (((c ^ (d & 7)) << 4)));
        CP_ASYNC16(sb + 32768 + off, (const char*)(g_wp + 5*16384) + (idx << 4));
    }
    CP_COMMIT();
    if (tid < 128) pb_s[tid] = opb[tid];

    CP_WAIT1();          // ts (older group) complete; W may still be in flight
    __syncthreads();

    // ---- LN over d per j: read column from ts via LDS ----
    const int jj = tid & 63, qq4 = tid >> 6;
    float v[32];
    {
        const __half* tsm = (const __half*)smb;
        float s = 0.f, ss = 0.f;
        #pragma unroll
        for (int t = 0; t < 32; t++){
            float x = __half2float(tsm[(qq4*32 + t)*64 + jj]);
            v[t] = x;
            s += x; ss += x*x;
        }
        sred[qq4][jj] = s; qred[qq4][jj] = ss;
    }
    __syncthreads();
    if (tid < 64){
        int j = tid;
        float S  = sred[0][j] + sred[1][j] + sred[2][j] + sred[3][j];
        float SS = qred[0][j] + qred[1][j] + qred[2][j] + qred[3][j];
        float m  = S * (1.f/128.f);
        float vv = fmaxf(SS * (1.f/128.f) - m*m, 0.f);
        mean_s[j] = m;
        inv_s[j]  = rsqrtf(vv + 1e-5f);
    }
    __syncthreads();
    // pack phase: overwrites ts region (all ts reads completed before the syncs above)
    {
        float m = mean_s[jj], iv = inv_s[jj];
        #pragma unroll
        for (int cc = 0; cc < 8; cc++){
            int c = qq4*8 + cc;
            int e = qq4*32 + cc*4;
            uint4 pv;
            uint32_t* pp = (uint32_t*)&pv;
            #pragma unroll
            for (int t = 0; t < 4; t++){
                float y = (v[cc*4 + t] - m)*iv*onw[e + t] + onb[e + t];
                pp[t] = pk_split(y);
            }
            uint32_t off = (uint32_t)(jj*512 + (((c ^ (jj & 7)) << 4)));
            *(uint4*)(smb + off) = pv;
        }
    }
    CP_WAIT0();
    __syncthreads();

    float acc[2][4][4];
    #pragma unroll
    for (int a = 0; a < 2; a++)
        #pragma unroll
        for (int b = 0; b < 4; b++)
            #pragma unroll
            for (int q = 0; q < 4; q++) acc[a][b][q] = 0.f;

    #pragma unroll 1
    for (int fkk = 0; fkk < 16; fkk++){
        uint32_t ap[2][4];
        #pragma unroll
        for (int mt = 0; mt < 2; mt++){
            int r = wm*32 + mt*16 + (lane & 15);
            int c = fkk*2 + (lane >> 4);
            ldsm4(ap[mt], sb + (uint32_t)(r*512 + (((c ^ (r & 7)) << 4))));
        }
        uint32_t bp[4][2];
        #pragma unroll
        for (int nt = 0; nt < 4; nt++){
            int l = lane & 15;
            int n = wn*32 + nt*8 + (l & 7);
            int c = fkk*2 + (l >> 3);
            ldsm2(bp[nt], sb + 32768 + (uint32_t)(n*512 + (((c ^ (n & 7)) << 4))));
        }
        #pragma unroll
        for (int mt = 0; mt < 2; mt++)
            #pragma unroll
            for (int nt = 0; nt < 4; nt++)
                mma_f16(acc[mt][nt], ap[mt], bp[nt]);
    }

    // epilogue: (acc + opb) * gate(fp16), direct global loads/stores
    #pragma unroll
    for (int mt = 0; mt < 2; mt++)
        #pragma unroll
        for (int nt = 0; nt < 4; nt++)
            #pragma unroll
            for (int qq = 0; qq < 2; qq++){
                int j = wm*32 + mt*16 + (lane >> 2) + qq*8;
                int n = wn*32 + nt*8 + ((lane & 3) << 1);
                size_t base = (size_t)(row0 + j)*DDIM + n;
                float2 g2 = __half22float2(*(const __half2*)&g_gate[base]);
                float2 o;
                o.x = (acc[mt][nt][qq*2+0] + pb_s[n+0]) * g2.x;
                o.y = (acc[mt][nt][qq*2+1] + pb_s[n+1]) * g2.y;
                *(float2*)&out[base] = o;
            }
}

extern "C" void kernel_launch(void* const* d_in, const int* in_sizes, int n_in,
                              void* d_out, int out_size)
{
    const float* pair = (const float*)d_in[0];
    const float* mask = (const float*)d_in[1];
    const float* nw   = (const float*)d_in[2];
    const float* nb   = (const float*)d_in[3];
    const float* lpw  = (const float*)d_in[4];
    const float* lpb  = (const float*)d_in[5];
    const float* lgw  = (const float*)d_in[6];
    const float* lgb  = (const float*)d_in[7];
    const float* rpw  = (const float*)d_in[8];
    const float* rpb  = (const float*)d_in[9];
    const float* rgw  = (const float*)d_in[10];
    const float* rgb  = (const float*)d_in[11];
    const float* onw  = (const float*)d_in[12];
    const float* onb  = (const float*)d_in[13];
    const float* opw  = (const float*)d_in[14];
    const float* opb  = (const float*)d_in[15];
    const float* ogw  = (const float*)d_in[16];
    const float* ogb  = (const float*)d_in[17];
    float* out = (float*)d_out;

    const int smem1 = 98304 + 1024;
    const int smem2 = 3*K2_BUF + 256;
    const int smem3 = 98304 + 1024;
    cudaFuncSetAttribute(k1_tc,  cudaFuncAttributeMaxDynamicSharedMemorySize, smem1);
    cudaFuncSetAttribute(k2_mma, cudaFuncAttributeMaxDynamicSharedMemorySize, smem2);
    cudaFuncSetAttribute(k3_tc,  cudaFuncAttributeMaxDynamicSharedMemorySize, smem3);

    k0_prep<<<dim3(64, 6), 256>>>(lpw, lgw, rpw, rgw, ogw, opw);

    k1_tc<<<NN/64, 256, smem1>>>(pair, mask, nw, nb, lpb, lgb, rpb, rgb, ogb);

    dim3 g2(32, 128);   // x = i-tile(4) x j-tile(8): consecutive blocks share the A tile in L2
    k2_mma<<<g2, 256, smem2>>>();

    k3_tc<<<NN/64, 256, smem3>>>(onw, onb, opb, out);
}

// round 13
// speedup vs baseline: 1.0023x; 1.0023x over previous
#include <cuda_runtime.h>
#include <cuda_fp16.h>
#include <cstdint>

#define NDIM 512
#define DDIM 128
#define NN (NDIM*NDIM)

// ---------------- scratch (device globals; no allocation allowed) ----------------
// packed fp16 tensors: each uint32 = (lo16<<16)|hi16 along fake-k axis
__device__ __align__(256) uint32_t g_lP[(size_t)DDIM*NN];   // left, dup-packed
__device__ __align__(256) uint32_t g_rP[(size_t)DDIM*NN];   // right, split-packed
__device__ __align__(256) __half g_gate[(size_t)NN*DDIM];   // fp16 gate
__device__ __align__(256) __half g_accT[(size_t)DDIM*NN];   // fp16 [d][i][j]
// pre-packed weights (dup fp16): 0=lp 1=lg 2=rp 3=rg 4=og 5=op
__device__ __align__(256) uint32_t g_wp[6*16384];

__device__ __forceinline__ float sigf(float x){ return 1.0f/(1.0f+__expf(-x)); }

__device__ __forceinline__ uint32_t pk_split(float v){
    __half h = __float2half_rn(v);
    __half l = __float2half_rn(v - __half2float(h));
    return (uint32_t)__half_as_ushort(h) | ((uint32_t)__half_as_ushort(l) << 16);
}
__device__ __forceinline__ uint32_t pk_dup(float v){
    uint32_t h = (uint32_t)__half_as_ushort(__float2half_rn(v));
    return h | (h << 16);
}

__device__ __forceinline__ uint32_t smem_u32(const void* p){
    uint32_t a;
    asm("{ .reg .u64 t; cvta.to.shared.u64 t, %1; cvt.u32.u64 %0, t; }" : "=r"(a) : "l"(p));
    return a;
}

// ---------------- baseline-PTX tensor-core helpers (fp16) ----------------
__device__ __forceinline__ void ldsm4(uint32_t (&r)[4], uint32_t a){
    asm volatile("ldmatrix.sync.aligned.m8n8.x4.shared.b16 {%0,%1,%2,%3}, [%4];"
        : "=r"(r[0]), "=r"(r[1]), "=r"(r[2]), "=r"(r[3]) : "r"(a));
}
__device__ __forceinline__ void ldsm2(uint32_t (&r)[2], uint32_t a){
    asm volatile("ldmatrix.sync.aligned.m8n8.x2.shared.b16 {%0,%1}, [%2];"
        : "=r"(r[0]), "=r"(r[1]) : "r"(a));
}
__device__ __forceinline__ void mma_f16(float (&c)[4], const uint32_t (&a)[4], const uint32_t (&b)[2]){
    asm volatile("mma.sync.aligned.m16n8k16.row.col.f32.f16.f16.f32 "
        "{%0,%1,%2,%3}, {%4,%5,%6,%7}, {%8,%9}, {%0,%1,%2,%3};"
        : "+f"(c[0]), "+f"(c[1]), "+f"(c[2]), "+f"(c[3])
        : "r"(a[0]), "r"(a[1]), "r"(a[2]), "r"(a[3]), "r"(b[0]), "r"(b[1]));
}
#define CP_ASYNC16(dst, src) \
    asm volatile("cp.async.cg.shared.global [%0], [%1], 16;" :: "r"(dst), "l"(src) : "memory")
#define CP_COMMIT() asm volatile("cp.async.commit_group;" ::: "memory")
#define CP_WAIT0()  asm volatile("cp.async.wait_group 0;" ::: "memory")
#define CP_WAIT1()  asm volatile("cp.async.wait_group 1;" ::: "memory")
#define CP_WAIT2()  asm volatile("cp.async.wait_group 2;" ::: "memory")

// ---------------- Kernel 0: pre-pack weights (dup fp16) ----------------
__global__ void k0_prep(const float* __restrict__ lpw, const float* __restrict__ lgw,
                        const float* __restrict__ rpw, const float* __restrict__ rgw,
                        const float* __restrict__ ogw, const float* __restrict__ opw)
{
    const float* srcs[6] = {lpw, lgw, rpw, rgw, ogw, opw};
    int m = blockIdx.y;
    int idx = blockIdx.x * 256 + threadIdx.x;
    g_wp[m*16384 + idx] = pk_dup(srcs[m][idx]);
}

// ================= Kernel 1: LN + 5 gated projections (64-row tiles, 2 CTA/SM) ==========
// smem: A packed [0,32K) 64 rows x 512B ; W packed [32K,96K) 128 rows x 512B
//       st (uint32 staging) overlays the W region
__global__ void __launch_bounds__(256, 2)
k1_tc(const float* __restrict__ pair, const float* __restrict__ mask,
      const float* __restrict__ nw,  const float* __restrict__ nb,
      const float* __restrict__ lpb, const float* __restrict__ lgb,
      const float* __restrict__ rpb, const float* __restrict__ rgb,
      const float* __restrict__ ogb)
{
    extern __shared__ char smraw[];
    char* smb = (char*)(((uintptr_t)smraw + 1023) & ~(uintptr_t)1023);
    const uint32_t sb = smem_u32(smb);
    uint32_t* st = (uint32_t*)(smb + 32768);
    __shared__ float mask_s[64];
    __shared__ float pb_s[128], gb_s[128];

    const int tid  = threadIdx.x;
    const int lane = tid & 31;
    const int wid  = tid >> 5;
    const int wm   = wid & 1;
    const int wn   = wid >> 1;
    const int row0 = blockIdx.x * 64;
    const int i_idx = row0 >> 9;
    const int k0    = row0 & 511;

    auto loadW = [&](const uint32_t* src){
        #pragma unroll
        for (int t = 0; t < 16; t++){
            int idx = tid + (t << 8);          // 0..4095 16B chunks
            int d = idx >> 5;
            int c = idx & 31;
            uint32_t off = (uint32_t)(d*512 + (((c ^ (d & 7)) << 4)));
            CP_ASYNC16(sb + 32768 + off, (const char*)src + (idx << 4));
        }
        CP_COMMIT();
    };

    // prefetch first weight (lp) — overlapped with LN below
    loadW(g_wp);
    if (tid < 64) mask_s[tid] = mask[row0 + tid];

    // ---- LN from registers (4 threads per row), write packed-split A ----
    {
        int row = tid >> 2, q = tid & 3;
        const float4* pr = (const float4*)(pair + (size_t)(row0 + row)*128 + q*32);
        float v[32];
        float s = 0.f, ss = 0.f;
        #pragma unroll
        for (int t = 0; t < 8; t++){
            float4 x = pr[t];
            v[t*4+0] = x.x; v[t*4+1] = x.y; v[t*4+2] = x.z; v[t*4+3] = x.w;
            s  += x.x + x.y + x.z + x.w;
            ss += x.x*x.x + x.y*x.y + x.z*x.z + x.w*x.w;
        }
        s  += __shfl_xor_sync(0xFFFFFFFFu, s, 1);
        ss += __shfl_xor_sync(0xFFFFFFFFu, ss, 1);
        s  += __shfl_xor_sync(0xFFFFFFFFu, s, 2);
        ss += __shfl_xor_sync(0xFFFFFFFFu, ss, 2);
        float m  = s * (1.f/128.f);
        float vv = fmaxf(ss * (1.f/128.f) - m*m, 0.f);
        float iv = rsqrtf(vv + 1e-5f);
        #pragma unroll
        for (int cc = 0; cc < 8; cc++){
            int c = q*8 + cc;
            int e = q*32 + cc*4;
            uint4 pv;
            uint32_t* pp = (uint32_t*)&pv;
            #pragma unroll
            for (int t = 0; t < 4; t++){
                float y = (v[cc*4 + t] - m)*iv*nw[e + t] + nb[e + t];
                pp[t] = pk_split(y);
            }
            uint32_t off = (uint32_t)(row*512 + (((c ^ (row & 7)) << 4)));
            *(uint4*)(smb + off) = pv;
        }
    }

    // GEMM: A packed [0,32K), W packed [32K,96K). 1 MMA per (fkk,mt,nt).
    auto gemmW = [&](float (&acc)[2][4][4]){
        #pragma unroll
        for (int a = 0; a < 2; a++)
            #pragma unroll
            for (int b = 0; b < 4; b++)
                #pragma unroll
                for (int q = 0; q < 4; q++) acc[a][b][q] = 0.f;
        #pragma unroll 1
        for (int fkk = 0; fkk < 16; fkk++){
            uint32_t ap[2][4];
            #pragma unroll
            for (int mt = 0; mt < 2; mt++){
                int r = wm*32 + mt*16 + (lane & 15);
                int c = fkk*2 + (lane >> 4);
                ldsm4(ap[mt], sb + (uint32_t)(r*512 + (((c ^ (r & 7)) << 4))));
            }
            uint32_t bp[4][2];
            #pragma unroll
            for (int nt = 0; nt < 4; nt++){
                int l = lane & 15;
                int n = wn*32 + nt*8 + (l & 7);
                int c = fkk*2 + (l >> 3);
                ldsm2(bp[nt], sb + 32768 + (uint32_t)(n*512 + (((c ^ (n & 7)) << 4))));
            }
            #pragma unroll
            for (int mt = 0; mt < 2; mt++)
                #pragma unroll
                for (int nt = 0; nt < 4; nt++)
                    mma_f16(acc[mt][nt], ap[mt], bp[nt]);
        }
    };

    // ---- passes A (left, dup-packed out) / B (right, split-packed out) ----
    #pragma unroll 1
    for (int pa = 0; pa < 2; pa++){
        if (pa) loadW(g_wp + 2*16384);
        if (tid < 128){
            pb_s[tid] = pa ? rpb[tid] : lpb[tid];
            gb_s[tid] = pa ? rgb[tid] : lgb[tid];
        }
        CP_WAIT0();
        __syncthreads();
        float accp[2][4][4];
        gemmW(accp);
        __syncthreads();

        loadW(g_wp + (pa*2+1)*16384);
        CP_WAIT0();
        __syncthreads();
        float accg[2][4][4];
        gemmW(accg);
        __syncthreads();

        #pragma unroll
        for (int mt = 0; mt < 2; mt++)
            #pragma unroll
            for (int nt = 0; nt < 4; nt++)
                #pragma unroll
                for (int q = 0; q < 4; q++){
                    int m = wm*32 + mt*16 + (lane >> 2) + ((q >> 1) << 3);
                    int n = wn*32 + nt*8 + ((lane & 3) << 1) + (q & 1);
                    float x = accp[mt][nt][q] + pb_s[n];
                    float g = accg[mt][nt][q] + gb_s[n];
                    float y = x * sigf(g) * mask_s[m];
                    st[m*129 + n] = pa ? pk_split(y) : pk_dup(y);
                }
        __syncthreads();

        // transpose write: packed [d][i][k]
        {
            uint32_t* gP = pa ? g_rP : g_lP;
            int dd = tid >> 1, half = tid & 1;
            uint4 o[8];
            uint32_t* op = (uint32_t*)o;
            #pragma unroll
            for (int kk = 0; kk < 32; kk++)
                op[kk] = st[(half*32 + kk)*129 + dd];
            uint32_t* dst = gP + ((size_t)dd*NDIM + i_idx)*NDIM + k0 + half*32;
            #pragma unroll
            for (int q = 0; q < 8; q++)
                *(uint4*)(dst + q*4) = o[q];
        }
        __syncthreads();
    }

    // ---- pass C: output gate (direct fp16 stores) ----
    loadW(g_wp + 4*16384);
    if (tid < 128) pb_s[tid] = ogb[tid];
    CP_WAIT0();
    __syncthreads();
    {
        float acc[2][4][4];
        gemmW(acc);
        #pragma unroll
        for (int mt = 0; mt < 2; mt++)
            #pragma unroll
            for (int nt = 0; nt < 4; nt++)
                #pragma unroll
                for (int qq = 0; qq < 2; qq++){
                    int m = wm*32 + mt*16 + (lane >> 2) + qq*8;
                    int n = wn*32 + nt*8 + ((lane & 3) << 1);
                    float gx = sigf(acc[mt][nt][qq*2+0] + pb_s[n+0]);
                    float gy = sigf(acc[mt][nt][qq*2+1] + pb_s[n+1]);
                    *(__half2*)&g_gate[(size_t)(row0 + m)*DDIM + n] = __floats2half2_rn(gx, gy);
                }
    }
}

// ================= Kernel 2: einsum, 128x64 tiles, K32 chunks, 3-stage, 3 CTA/SM =========
// per buffer (24KB): A packed [0,16K) 128x128B ; B packed [16K,24K) 64x128B
#define K2_BUF 24576

__global__ void __launch_bounds__(256, 3)
k2_mma()
{
    extern __shared__ char smraw[];
    char* smb = (char*)(((uintptr_t)smraw + 127) & ~(uintptr_t)127);
    const uint32_t sb = smem_u32(smb);

    const int tid  = threadIdx.x;
    const int lane = tid & 31;
    const int wid  = tid >> 5;
    const int d    = blockIdx.y;
    const int i0   = (blockIdx.x >> 3) * 128;
    const int j0   = (blockIdx.x & 7) * 64;
    const int wm   = wid & 3;          // 4 m-groups of 32 rows
    const int wn   = wid >> 2;         // 2 n-groups of 32 cols

    auto load_chunk = [&](int kc, int b){
        #pragma unroll
        for (int t = 0; t < 6; t++){
            int idx = tid + (t << 8);          // 0..1535 16B chunks
            const uint32_t* src;
            int rb, r;
            uint32_t roff;
            if (idx < 1024){
                src = g_lP; rb = i0; r = idx >> 3; roff = 0u;
            } else {
                int x = idx - 1024;
                src = g_rP; rb = j0; r = x >> 3; roff = 16384u;
            }
            int c = idx & 7;
            const void* gp = src + ((size_t)d*NDIM + rb + r)*NDIM + kc + (c << 2);
            uint32_t dst = sb + b*K2_BUF + roff + (r << 7) + (((c ^ (r & 7)) << 4));
            CP_ASYNC16(dst, gp);
        }
        CP_COMMIT();
    };

    float acc[2][4][4];
    #pragma unroll
    for (int a = 0; a < 2; a++)
        #pragma unroll
        for (int b = 0; b < 4; b++)
            #pragma unroll
            for (int q = 0; q < 4; q++) acc[a][b][q] = 0.f;

    load_chunk(0, 0);
    load_chunk(32, 1);
    load_chunk(64, 2);

    int cs = 0;
    #pragma unroll 1
    for (int t = 0; t < 16; t++){
        if (t <= 13)      CP_WAIT2();
        else if (t == 14) CP_WAIT1();
        else              CP_WAIT0();
        __syncthreads();

        const uint32_t base = sb + cs*K2_BUF;
        #pragma unroll
        for (int fkk = 0; fkk < 4; fkk++){
            uint32_t ap[2][4], bp[4][2];
            #pragma unroll
            for (int mt = 0; mt < 2; mt++){
                int m = wm*32 + mt*16 + (lane & 15);
                int c = fkk*2 + (lane >> 4);
                ldsm4(ap[mt], base + (uint32_t)((m << 7) + (((c ^ (m & 7)) << 4))));
            }
            #pragma unroll
            for (int nt = 0; nt < 4; nt++){
                int l = lane & 15;
                int n = wn*32 + nt*8 + (l & 7);
                int c = fkk*2 + (l >> 3);
                ldsm2(bp[nt], base + 16384 + (uint32_t)((n << 7) + (((c ^ (n & 7)) << 4))));
            }
            #pragma unroll
            for (int mt = 0; mt < 2; mt++)
                #pragma unroll
                for (int nt = 0; nt < 4; nt++)
                    mma_f16(acc[mt][nt], ap[mt], bp[nt]);
        }
        __syncthreads();
        if (t + 3 < 16) load_chunk((t + 3)*32, cs);   // cs buffer just freed
        cs = (cs == 2) ? 0 : cs + 1;
    }

    // epilogue: write accT fp16 (half2 along j)
    #pragma unroll
    for (int mt = 0; mt < 2; mt++){
        int r0 = i0 + wm*32 + mt*16 + (lane >> 2);
        #pragma unroll
        for (int nt = 0; nt < 4; nt++){
            int c0 = j0 + wn*32 + nt*8 + (lane & 3)*2;
            __half* p0 = &g_accT[((size_t)d*NDIM + r0)*NDIM + c0];
            __half* p1 = &g_accT[((size_t)d*NDIM + r0 + 8)*NDIM + c0];
            *(__half2*)p0 = __floats2half2_rn(acc[mt][nt][0], acc[mt][nt][1]);
            *(__half2*)p1 = __floats2half2_rn(acc[mt][nt][2], acc[mt][nt][3]);
        }
    }
}

// ================= Kernel 3: LN(accT) @ opw.T + opb, times gate (64-j tiles, 2 CTA/SM) ====
// smem: A packed [0,32K) (accT staging ts overlays [0,16K) before pack phase)
//       W packed [32K,96K) (prefetched, separate cp.async group)
__global__ void __launch_bounds__(256, 2)
k3_tc(const float* __restrict__ onw, const float* __restrict__ onb,
      const float* __restrict__ opb, float* __restrict__ out)
{
    extern __shared__ char smraw[];
    char* smb = (char*)(((uintptr_t)smraw + 1023) & ~(uintptr_t)1023);
    const uint32_t sb = smem_u32(smb);
    __shared__ float pb_s[128];
    __shared__ float sred[4][64], qred[4][64];
    __shared__ float mean_s[64], inv_s[64];

    const int tid  = threadIdx.x;
    const int lane = tid & 31;
    const int wid  = tid >> 5;
    const int wm   = wid & 1;
    const int wn   = wid >> 1;
    const int i_idx = blockIdx.x >> 3;
    const int j0    = (blockIdx.x & 7) * 64;
    const int row0  = i_idx*NDIM + j0;

    // group 0: accT tile -> ts (overlays A region [0,16K)), fully coalesced
    #pragma unroll
    for (int t = 0; t < 4; t++){
        int idx = tid + (t << 8);          // 0..1023 16B chunks
        int d = idx >> 3;                  // row = d (128 rows x 128B)
        int c = idx & 7;
        CP_ASYNC16(sb + (uint32_t)(d*128 + c*16),
                   (const char*)(g_accT + (size_t)d*NN + row0) + c*16);
    }
    CP_COMMIT();

    // group 1: op weight prefetch
    #pragma unroll
    for (int t = 0; t < 16; t++){
        int idx = tid + (t << 8);
        int d = idx >> 5;
        int c = idx & 31;
        uint32_t off = (uint32_t)(d*512 + (((c ^ (d & 7)) << 4)));
        CP_ASYNC16(sb + 32768 + off, (const char*)(g_wp + 5*16384) + (idx << 4));
    }
    CP_COMMIT();
    if (tid < 128) pb_s[tid] = opb[tid];

    CP_WAIT1();          // ts (older group) complete; W may still be in flight
    __syncthreads();

    // ---- LN over d per j: read column from ts via LDS ----
    const int jj = tid & 63, qq4 = tid >> 6;
    float v[32];
    {
        const __half* tsm = (const __half*)smb;
        float s = 0.f, ss = 0.f;
        #pragma unroll
        for (int t = 0; t < 32; t++){
            float x = __half2float(tsm[(qq4*32 + t)*64 + jj]);
            v[t] = x;
            s += x; ss += x*x;
        }
        sred[qq4][jj] = s; qred[qq4][jj] = ss;
    }
    __syncthreads();
    if (tid < 64){
        int j = tid;
        float S  = sred[0][j] + sred[1][j] + sred[2][j] + sred[3][j];
        float SS = qred[0][j] + qred[1][j] + qred[2][j] + qred[3][j];
        float m  = S * (1.f/128.f);
        float vv = fmaxf(SS * (1.f/128.f) - m*m, 0.f);
        mean_s[j] = m;
        inv_s[j]  = rsqrtf(vv + 1e-5f);
    }
    __syncthreads();
    // pack phase: overwrites ts region (all ts reads completed before the syncs above)
    {
        float m = mean_s[jj], iv = inv_s[jj];
        #pragma unroll
        for (int cc = 0; cc < 8; cc++){
            int c = qq4*8 + cc;
            int e = qq4*32 + cc*4;
            uint4 pv;
            uint32_t* pp = (uint32_t*)&pv;
            #pragma unroll
            for (int t = 0; t < 4; t++){
                float y = (v[cc*4 + t] - m)*iv*onw[e + t] + onb[e + t];
                pp[t] = pk_split(y);
            }
            uint32_t off = (uint32_t)(jj*512 + (((c ^ (jj & 7)) << 4)));
            *(uint4*)(smb + off) = pv;
        }
    }
    CP_WAIT0();
    __syncthreads();

    float acc[2][4][4];
    #pragma unroll
    for (int a = 0; a < 2; a++)
        #pragma unroll
        for (int b = 0; b < 4; b++)
            #pragma unroll
            for (int q = 0; q < 4; q++) acc[a][b][q] = 0.f;

    #pragma unroll 1
    for (int fkk = 0; fkk < 16; fkk++){
        uint32_t ap[2][4];
        #pragma unroll
        for (int mt = 0; mt < 2; mt++){
            int r = wm*32 + mt*16 + (lane & 15);
            int c = fkk*2 + (lane >> 4);
            ldsm4(ap[mt], sb + (uint32_t)(r*512 + (((c ^ (r & 7)) << 4))));
        }
        uint32_t bp[4][2];
        #pragma unroll
        for (int nt = 0; nt < 4; nt++){
            int l = lane & 15;
            int n = wn*32 + nt*8 + (l & 7);
            int c = fkk*2 + (l >> 3);
            ldsm2(bp[nt], sb + 32768 + (uint32_t)(n*512 + (((c ^ (n & 7)) << 4))));
        }
        #pragma unroll
        for (int mt = 0; mt < 2; mt++)
            #pragma unroll
            for (int nt = 0; nt < 4; nt++)
                mma_f16(acc[mt][nt], ap[mt], bp[nt]);
    }

    // epilogue: (acc + opb) * gate(fp16), direct global loads/stores
    #pragma unroll
    for (int mt = 0; mt < 2; mt++)
        #pragma unroll
        for (int nt = 0; nt < 4; nt++)
            #pragma unroll
            for (int qq = 0; qq < 2; qq++){
                int j = wm*32 + mt*16 + (lane >> 2) + qq*8;
                int n = wn*32 + nt*8 + ((lane & 3) << 1);
                size_t base = (size_t)(row0 + j)*DDIM + n;
                float2 g2 = __half22float2(*(const __half2*)&g_gate[base]);
                float2 o;
                o.x = (acc[mt][nt][qq*2+0] + pb_s[n+0]) * g2.x;
                o.y = (acc[mt][nt][qq*2+1] + pb_s[n+1]) * g2.y;
                *(float2*)&out[base] = o;
            }
}

extern "C" void kernel_launch(void* const* d_in, const int* in_sizes, int n_in,
                              void* d_out, int out_size)
{
    const float* pair = (const float*)d_in[0];
    const float* mask = (const float*)d_in[1];
    const float* nw   = (const float*)d_in[2];
    const float* nb   = (const float*)d_in[3];
    const float* lpw  = (const float*)d_in[4];
    const float* lpb  = (const float*)d_in[5];
    const float* lgw  = (const float*)d_in[6];
    const float* lgb  = (const float*)d_in[7];
    const float* rpw  = (const float*)d_in[8];
    const float* rpb  = (const float*)d_in[9];
    const float* rgw  = (const float*)d_in[10];
    const float* rgb  = (const float*)d_in[11];
    const float* onw  = (const float*)d_in[12];
    const float* onb  = (const float*)d_in[13];
    const float* opw  = (const float*)d_in[14];
    const float* opb  = (const float*)d_in[15];
    const float* ogw  = (const float*)d_in[16];
    const float* ogb  = (const float*)d_in[17];
    float* out = (float*)d_out;

    const int smem1 = 98304 + 1024;
    const int smem2 = 3*K2_BUF + 256;
    const int smem3 = 98304 + 1024;
    cudaFuncSetAttribute(k1_tc,  cudaFuncAttributeMaxDynamicSharedMemorySize, smem1);
    cudaFuncSetAttribute(k2_mma, cudaFuncAttributeMaxDynamicSharedMemorySize, smem2);
    cudaFuncSetAttribute(k3_tc,  cudaFuncAttributeMaxDynamicSharedMemorySize, smem3);

    k0_prep<<<dim3(64, 6), 256>>>(lpw, lgw, rpw, rgw, ogw, opw);

    k1_tc<<<NN/64, 256, smem1>>>(pair, mask, nw, nb, lpb, lgb, rpb, rgb, ogb);

    dim3 g2(32, 128);   // x = i-tile(4) x j-tile(8): consecutive blocks share the A tile in L2
    k2_mma<<<g2, 256, smem2>>>();

    k3_tc<<<NN/64, 256, smem3>>>(onw, onb, opb, out);
}

// round 14
// speedup vs baseline: 1.4212x; 1.4179x over previous
#include <cuda_runtime.h>
#include <cuda_fp16.h>
#include <cstdint>

#define NDIM 512
#define DDIM 128
#define NN (NDIM*NDIM)

// ---------------- scratch (device globals; no allocation allowed) ----------------
__device__ __align__(256) __half g_lH[(size_t)DDIM*NN];     // left  [d][i][k] fp16
__device__ __align__(256) __half g_rH[(size_t)DDIM*NN];     // right [d][j][k] fp16
__device__ __align__(256) __half g_gate[(size_t)NN*DDIM];   // fp16 gate
__device__ __align__(256) __half g_accT[(size_t)DDIM*NN];   // fp16 [d][i][j]
// plain fp16 weights: 0=lp 1=lg 2=rp 3=rg 4=og 5=op  (row-major [n][k])
__device__ __align__(256) __half g_wh[6*16384];

__device__ __forceinline__ float sigf(float x){ return 1.0f/(1.0f+__expf(-x)); }

__device__ __forceinline__ uint32_t smem_u32(const void* p){
    uint32_t a;
    asm("{ .reg .u64 t; cvta.to.shared.u64 t, %1; cvt.u32.u64 %0, t; }" : "=r"(a) : "l"(p));
    return a;
}

// ---------------- baseline-PTX tensor-core helpers (fp16) ----------------
__device__ __forceinline__ void ldsm4(uint32_t (&r)[4], uint32_t a){
    asm volatile("ldmatrix.sync.aligned.m8n8.x4.shared.b16 {%0,%1,%2,%3}, [%4];"
        : "=r"(r[0]), "=r"(r[1]), "=r"(r[2]), "=r"(r[3]) : "r"(a));
}
__device__ __forceinline__ void ldsm2(uint32_t (&r)[2], uint32_t a){
    asm volatile("ldmatrix.sync.aligned.m8n8.x2.shared.b16 {%0,%1}, [%2];"
        : "=r"(r[0]), "=r"(r[1]) : "r"(a));
}
__device__ __forceinline__ void mma_f16(float (&c)[4], const uint32_t (&a)[4], const uint32_t (&b)[2]){
    asm volatile("mma.sync.aligned.m16n8k16.row.col.f32.f16.f16.f32 "
        "{%0,%1,%2,%3}, {%4,%5,%6,%7}, {%8,%9}, {%0,%1,%2,%3};"
        : "+f"(c[0]), "+f"(c[1]), "+f"(c[2]), "+f"(c[3])
        : "r"(a[0]), "r"(a[1]), "r"(a[2]), "r"(a[3]), "r"(b[0]), "r"(b[1]));
}
#define CP_ASYNC16(dst, src) \
    asm volatile("cp.async.cg.shared.global [%0], [%1], 16;" :: "r"(dst), "l"(src) : "memory")
#define CP_COMMIT() asm volatile("cp.async.commit_group;" ::: "memory")
#define CP_WAIT0()  asm volatile("cp.async.wait_group 0;" ::: "memory")
#define CP_WAIT1()  asm volatile("cp.async.wait_group 1;" ::: "memory")
#define CP_WAIT2()  asm volatile("cp.async.wait_group 2;" ::: "memory")

// ---------------- Kernel 0: weights -> fp16 ----------------
__global__ void k0_prep(const float* __restrict__ lpw, const float* __restrict__ lgw,
                        const float* __restrict__ rpw, const float* __restrict__ rgw,
                        const float* __restrict__ ogw, const float* __restrict__ opw)
{
    const float* srcs[6] = {lpw, lgw, rpw, rgw, ogw, opw};
    int m = blockIdx.y;
    int idx = blockIdx.x * 256 + threadIdx.x;
    g_wh[m*16384 + idx] = __float2half_rn(srcs[m][idx]);
}

// ================= Kernel 1: LN + 5 gated projections (64-row tiles, 2 CTA/SM) ==========
// smem: A fp16 [0,16K) 64 rows x 256B ; W fp16 [16K,48K) 128 rows x 256B ;
//       st uint32 [48K, 48K+33024)
#define K1_ST 49152
__global__ void __launch_bounds__(256, 2)
k1_tc(const float* __restrict__ pair, const float* __restrict__ mask,
      const float* __restrict__ nw,  const float* __restrict__ nb,
      const float* __restrict__ lpb, const float* __restrict__ lgb,
      const float* __restrict__ rpb, const float* __restrict__ rgb,
      const float* __restrict__ ogb)
{
    extern __shared__ char smraw[];
    char* smb = (char*)(((uintptr_t)smraw + 1023) & ~(uintptr_t)1023);
    const uint32_t sb = smem_u32(smb);
    uint32_t* st = (uint32_t*)(smb + K1_ST);
    __shared__ float mask_s[64];
    __shared__ float pb_s[128], gb_s[128];

    const int tid  = threadIdx.x;
    const int lane = tid & 31;
    const int wid  = tid >> 5;
    const int wm   = wid & 1;
    const int wn   = wid >> 1;
    const int row0 = blockIdx.x * 64;
    const int i_idx = row0 >> 9;
    const int k0    = row0 & 511;

    auto loadW = [&](const __half* src){
        #pragma unroll
        for (int t = 0; t < 8; t++){
            int idx = tid + (t << 8);          // 0..2047 16B chunks
            int d = idx >> 4;
            int c = idx & 15;
            uint32_t off = (uint32_t)(d*256 + (((c ^ (d & 7)) << 4)));
            CP_ASYNC16(sb + 16384 + off, (const char*)src + (idx << 4));
        }
        CP_COMMIT();
    };

    // prefetch first weight (lp) — overlapped with LN below
    loadW(g_wh);
    if (tid < 64) mask_s[tid] = mask[row0 + tid];

    // ---- LN from registers (4 threads per row), write fp16 A ----
    {
        int row = tid >> 2, q = tid & 3;
        const float4* pr = (const float4*)(pair + (size_t)(row0 + row)*128 + q*32);
        float v[32];
        float s = 0.f, ss = 0.f;
        #pragma unroll
        for (int t = 0; t < 8; t++){
            float4 x = pr[t];
            v[t*4+0] = x.x; v[t*4+1] = x.y; v[t*4+2] = x.z; v[t*4+3] = x.w;
            s  += x.x + x.y + x.z + x.w;
            ss += x.x*x.x + x.y*x.y + x.z*x.z + x.w*x.w;
        }
        s  += __shfl_xor_sync(0xFFFFFFFFu, s, 1);
        ss += __shfl_xor_sync(0xFFFFFFFFu, ss, 1);
        s  += __shfl_xor_sync(0xFFFFFFFFu, s, 2);
        ss += __shfl_xor_sync(0xFFFFFFFFu, ss, 2);
        float m  = s * (1.f/128.f);
        float vv = fmaxf(ss * (1.f/128.f) - m*m, 0.f);
        float iv = rsqrtf(vv + 1e-5f);
        #pragma unroll
        for (int cc = 0; cc < 4; cc++){
            int c = q*4 + cc;
            int e = q*32 + cc*8;
            uint4 pv;
            unsigned short* pp = (unsigned short*)&pv;
            #pragma unroll
            for (int t = 0; t < 8; t++){
                float y = (v[cc*8 + t] - m)*iv*nw[e + t] + nb[e + t];
                pp[t] = __half_as_ushort(__float2half_rn(y));
            }
            uint32_t off = (uint32_t)(row*256 + (((c ^ (row & 7)) << 4)));
            *(uint4*)(smb + off) = pv;
        }
    }

    // GEMM: A fp16 [0,16K), W fp16 [16K,48K). K=128 -> 8 fkk.
    auto gemmW = [&](float (&acc)[2][4][4]){
        #pragma unroll
        for (int a = 0; a < 2; a++)
            #pragma unroll
            for (int b = 0; b < 4; b++)
                #pragma unroll
                for (int q = 0; q < 4; q++) acc[a][b][q] = 0.f;
        #pragma unroll 1
        for (int fkk = 0; fkk < 8; fkk++){
            uint32_t ap[2][4];
            #pragma unroll
            for (int mt = 0; mt < 2; mt++){
                int r = wm*32 + mt*16 + (lane & 15);
                int c = fkk*2 + (lane >> 4);
                ldsm4(ap[mt], sb + (uint32_t)(r*256 + (((c ^ (r & 7)) << 4))));
            }
            uint32_t bp[4][2];
            #pragma unroll
            for (int nt = 0; nt < 4; nt++){
                int l = lane & 15;
                int n = wn*32 + nt*8 + (l & 7);
                int c = fkk*2 + (l >> 3);
                ldsm2(bp[nt], sb + 16384 + (uint32_t)(n*256 + (((c ^ (n & 7)) << 4))));
            }
            #pragma unroll
            for (int mt = 0; mt < 2; mt++)
                #pragma unroll
                for (int nt = 0; nt < 4; nt++)
                    mma_f16(acc[mt][nt], ap[mt], bp[nt]);
        }
    };

    // ---- passes A (left) / B (right) ----
    #pragma unroll 1
    for (int pa = 0; pa < 2; pa++){
        if (pa) loadW(g_wh + 2*16384);
        if (tid < 128){
            pb_s[tid] = pa ? rpb[tid] : lpb[tid];
            gb_s[tid] = pa ? rgb[tid] : lgb[tid];
        }
        CP_WAIT0();
        __syncthreads();
        float accp[2][4][4];
        gemmW(accp);
        __syncthreads();

        loadW(g_wh + (pa*2+1)*16384);
        CP_WAIT0();
        __syncthreads();
        float accg[2][4][4];
        gemmW(accg);
        __syncthreads();

        #pragma unroll
        for (int mt = 0; mt < 2; mt++)
            #pragma unroll
            for (int nt = 0; nt < 4; nt++)
                #pragma unroll
                for (int q = 0; q < 4; q++){
                    int m = wm*32 + mt*16 + (lane >> 2) + ((q >> 1) << 3);
                    int n = wn*32 + nt*8 + ((lane & 3) << 1) + (q & 1);
                    float x = accp[mt][nt][q] + pb_s[n];
                    float g = accg[mt][nt][q] + gb_s[n];
                    float y = x * sigf(g) * mask_s[m];
                    st[m*129 + n] = (uint32_t)__half_as_ushort(__float2half_rn(y));
                }
        __syncthreads();

        // transpose write: fp16 [d][i][k]
        {
            __half* gH = pa ? g_rH : g_lH;
            int dd = tid >> 1, half = tid & 1;
            uint4 o[4];
            unsigned short* op = (unsigned short*)o;
            #pragma unroll
            for (int kk = 0; kk < 32; kk++)
                op[kk] = (unsigned short)st[(half*32 + kk)*129 + dd];
            __half* dst = gH + ((size_t)dd*NDIM + i_idx)*NDIM + k0 + half*32;
            #pragma unroll
            for (int q = 0; q < 4; q++)
                *(uint4*)(dst + q*8) = o[q];
        }
        __syncthreads();
    }

    // ---- pass C: output gate (direct fp16 stores) ----
    loadW(g_wh + 4*16384);
    if (tid < 128) pb_s[tid] = ogb[tid];
    CP_WAIT0();
    __syncthreads();
    {
        float acc[2][4][4];
        gemmW(acc);
        #pragma unroll
        for (int mt = 0; mt < 2; mt++)
            #pragma unroll
            for (int nt = 0; nt < 4; nt++)
                #pragma unroll
                for (int qq = 0; qq < 2; qq++){
                    int m = wm*32 + mt*16 + (lane >> 2) + qq*8;
                    int n = wn*32 + nt*8 + ((lane & 3) << 1);
                    float gx = sigf(acc[mt][nt][qq*2+0] + pb_s[n+0]);
                    float gy = sigf(acc[mt][nt][qq*2+1] + pb_s[n+1]);
                    *(__half2*)&g_gate[(size_t)(row0 + m)*DDIM + n] = __floats2half2_rn(gx, gy);
                }
    }
}

// ================= Kernel 2: einsum, 128x64 tiles, K64 chunks, 3-stage, 3 CTA/SM =========
// per buffer (24KB): A fp16 [0,16K) 128x128B ; B fp16 [16K,24K) 64x128B
#define K2_BUF 24576

__global__ void __launch_bounds__(256, 3)
k2_mma()
{
    extern __shared__ char smraw[];
    char* smb = (char*)(((uintptr_t)smraw + 127) & ~(uintptr_t)127);
    const uint32_t sb = smem_u32(smb);

    const int tid  = threadIdx.x;
    const int lane = tid & 31;
    const int wid  = tid >> 5;
    const int d    = blockIdx.y;
    const int i0   = (blockIdx.x >> 3) * 128;
    const int j0   = (blockIdx.x & 7) * 64;
    const int wm   = wid & 3;          // 4 m-groups of 32 rows
    const int wn   = wid >> 2;         // 2 n-groups of 32 cols

    auto load_chunk = [&](int kc, int b){
        #pragma unroll
        for (int t = 0; t < 6; t++){
            int idx = tid + (t << 8);          // 0..1535 16B chunks
            const __half* src;
            int rb, r;
            uint32_t roff;
            if (idx < 1024){
                src = g_lH; rb = i0; r = idx >> 3; roff = 0u;
            } else {
                int x = idx - 1024;
                src = g_rH; rb = j0; r = x >> 3; roff = 16384u;
            }
            int c = idx & 7;
            const void* gp = src + ((size_t)d*NDIM + rb + r)*NDIM + kc + (c << 3);
            uint32_t dst = sb + b*K2_BUF + roff + (r << 7) + (((c ^ (r & 7)) << 4));
            CP_ASYNC16(dst, gp);
        }
        CP_COMMIT();
    };

    float acc[2][4][4];
    #pragma unroll
    for (int a = 0; a < 2; a++)
        #pragma unroll
        for (int b = 0; b < 4; b++)
            #pragma unroll
            for (int q = 0; q < 4; q++) acc[a][b][q] = 0.f;

    load_chunk(0, 0);
    load_chunk(64, 1);
    load_chunk(128, 2);

    int cs = 0;
    #pragma unroll 1
    for (int t = 0; t < 8; t++){
        if (t <= 5)      CP_WAIT2();
        else if (t == 6) CP_WAIT1();
        else             CP_WAIT0();
        __syncthreads();

        const uint32_t base = sb + cs*K2_BUF;
        #pragma unroll
        for (int fkk = 0; fkk < 4; fkk++){
            uint32_t ap[2][4], bp[4][2];
            #pragma unroll
            for (int mt = 0; mt < 2; mt++){
                int m = wm*32 + mt*16 + (lane & 15);
                int c = fkk*2 + (lane >> 4);
                ldsm4(ap[mt], base + (uint32_t)((m << 7) + (((c ^ (m & 7)) << 4))));
            }
            #pragma unroll
            for (int nt = 0; nt < 4; nt++){
                int l = lane & 15;
                int n = wn*32 + nt*8 + (l & 7);
                int c = fkk*2 + (l >> 3);
                ldsm2(bp[nt], base + 16384 + (uint32_t)((n << 7) + (((c ^ (n & 7)) << 4))));
            }
            #pragma unroll
            for (int mt = 0; mt < 2; mt++)
                #pragma unroll
                for (int nt = 0; nt < 4; nt++)
                    mma_f16(acc[mt][nt], ap[mt], bp[nt]);
        }
        __syncthreads();
        if (t + 3 < 8) load_chunk((t + 3)*64, cs);   // cs buffer just freed
        cs = (cs == 2) ? 0 : cs + 1;
    }

    // epilogue: write accT fp16 (half2 along j)
    #pragma unroll
    for (int mt = 0; mt < 2; mt++){
        int r0 = i0 + wm*32 + mt*16 + (lane >> 2);
        #pragma unroll
        for (int nt = 0; nt < 4; nt++){
            int c0 = j0 + wn*32 + nt*8 + (lane & 3)*2;
            __half* p0 = &g_accT[((size_t)d*NDIM + r0)*NDIM + c0];
            __half* p1 = &g_accT[((size_t)d*NDIM + r0 + 8)*NDIM + c0];
            *(__half2*)p0 = __floats2half2_rn(acc[mt][nt][0], acc[mt][nt][1]);
            *(__half2*)p1 = __floats2half2_rn(acc[mt][nt][2], acc[mt][nt][3]);
        }
    }
}

// ================= Kernel 3: LN(accT) @ opw.T + opb, times gate (64-j tiles, 2 CTA/SM) ====
// smem: A fp16 [0,16K) ; W fp16 [16K,48K) ; ts [48K,64K)
#define K3_TS 49152
__global__ void __launch_bounds__(256, 2)
k3_tc(const float* __restrict__ onw, const float* __restrict__ onb,
      const float* __restrict__ opb, float* __restrict__ out)
{
    extern __shared__ char smraw[];
    char* smb = (char*)(((uintptr_t)smraw + 1023) & ~(uintptr_t)1023);
    const uint32_t sb = smem_u32(smb);
    __shared__ float pb_s[128];
    __shared__ float sred[4][64], qred[4][64];
    __shared__ float mean_s[64], inv_s[64];

    const int tid  = threadIdx.x;
    const int lane = tid & 31;
    const int wid  = tid >> 5;
    const int wm   = wid & 1;
    const int wn   = wid >> 1;
    const int i_idx = blockIdx.x >> 3;
    const int j0    = (blockIdx.x & 7) * 64;
    const int row0  = i_idx*NDIM + j0;

    // group 0: accT tile -> ts [48K,64K), fully coalesced
    #pragma unroll
    for (int t = 0; t < 4; t++){
        int idx = tid + (t << 8);          // 0..1023 16B chunks
        int d = idx >> 3;
        int c = idx & 7;
        CP_ASYNC16(sb + K3_TS + (uint32_t)(d*128 + c*16),
                   (const char*)(g_accT + (size_t)d*NN + row0) + (c << 4));
    }
    CP_COMMIT();

    // group 1: op weight prefetch -> [16K,48K)
    #pragma unroll
    for (int t = 0; t < 8; t++){
        int idx = tid + (t << 8);
        int d = idx >> 4;
        int c = idx & 15;
        uint32_t off = (uint32_t)(d*256 + (((c ^ (d & 7)) << 4)));
        CP_ASYNC16(sb + 16384 + off, (const char*)(g_wh + 5*16384) + (idx << 4));
    }
    CP_COMMIT();
    if (tid < 128) pb_s[tid] = opb[tid];

    CP_WAIT1();          // ts complete; W may still be in flight
    __syncthreads();

    // ---- LN over d per j ----
    const int jj = tid & 63, qq4 = tid >> 6;
    float v[32];
    {
        const __half* tsm = (const __half*)(smb + K3_TS);
        float s = 0.f, ss = 0.f;
        #pragma unroll
        for (int t = 0; t < 32; t++){
            float x = __half2float(tsm[(qq4*32 + t)*64 + jj]);
            v[t] = x;
            s += x; ss += x*x;
        }
        sred[qq4][jj] = s; qred[qq4][jj] = ss;
    }
    __syncthreads();
    if (tid < 64){
        int j = tid;
        float S  = sred[0][j] + sred[1][j] + sred[2][j] + sred[3][j];
        float SS = qred[0][j] + qred[1][j] + qred[2][j] + qred[3][j];
        float m  = S * (1.f/128.f);
        float vv = fmaxf(SS * (1.f/128.f) - m*m, 0.f);
        mean_s[j] = m;
        inv_s[j]  = rsqrtf(vv + 1e-5f);
    }
    __syncthreads();
    // pack phase: write fp16 A [0,16K)
    {
        float m = mean_s[jj], iv = inv_s[jj];
        #pragma unroll
        for (int cc = 0; cc < 4; cc++){
            int c = qq4*4 + cc;
            int e = qq4*32 + cc*8;
            uint4 pv;
            unsigned short* pp = (unsigned short*)&pv;
            #pragma unroll
            for (int t = 0; t < 8; t++){
                float y = (v[cc*8 + t] - m)*iv*onw[e + t] + onb[e + t];
                pp[t] = __half_as_ushort(__float2half_rn(y));
            }
            uint32_t off = (uint32_t)(jj*256 + (((c ^ (jj & 7)) << 4)));
            *(uint4*)(smb + off) = pv;
        }
    }
    CP_WAIT0();
    __syncthreads();

    float acc[2][4][4];
    #pragma unroll
    for (int a = 0; a < 2; a++)
        #pragma unroll
        for (int b = 0; b < 4; b++)
            #pragma unroll
            for (int q = 0; q < 4; q++) acc[a][b][q] = 0.f;

    #pragma unroll 1
    for (int fkk = 0; fkk < 8; fkk++){
        uint32_t ap[2][4];
        #pragma unroll
        for (int mt = 0; mt < 2; mt++){
            int r = wm*32 + mt*16 + (lane & 15);
            int c = fkk*2 + (lane >> 4);
            ldsm4(ap[mt], sb + (uint32_t)(r*256 + (((c ^ (r & 7)) << 4))));
        }
        uint32_t bp[4][2];
        #pragma unroll
        for (int nt = 0; nt < 4; nt++){
            int l = lane & 15;
            int n = wn*32 + nt*8 + (l & 7);
            int c = fkk*2 + (l >> 3);
            ldsm2(bp[nt], sb + 16384 + (uint32_t)(n*256 + (((c ^ (n & 7)) << 4))));
        }
        #pragma unroll
        for (int mt = 0; mt < 2; mt++)
            #pragma unroll
            for (int nt = 0; nt < 4; nt++)
                mma_f16(acc[mt][nt], ap[mt], bp[nt]);
    }

    // epilogue: (acc + opb) * gate(fp16), direct global loads/stores
    #pragma unroll
    for (int mt = 0; mt < 2; mt++)
        #pragma unroll
        for (int nt = 0; nt < 4; nt++)
            #pragma unroll
            for (int qq = 0; qq < 2; qq++){
                int j = wm*32 + mt*16 + (lane >> 2) + qq*8;
                int n = wn*32 + nt*8 + ((lane & 3) << 1);
                size_t base = (size_t)(row0 + j)*DDIM + n;
                float2 g2 = __half22float2(*(const __half2*)&g_gate[base]);
                float2 o;
                o.x = (acc[mt][nt][qq*2+0] + pb_s[n+0]) * g2.x;
                o.y = (acc[mt][nt][qq*2+1] + pb_s[n+1]) * g2.y;
                *(float2*)&out[base] = o;
            }
}

extern "C" void kernel_launch(void* const* d_in, const int* in_sizes, int n_in,
                              void* d_out, int out_size)
{
    const float* pair = (const float*)d_in[0];
    const float* mask = (const float*)d_in[1];
    const float* nw   = (const float*)d_in[2];
    const float* nb   = (const float*)d_in[3];
    const float* lpw  = (const float*)d_in[4];
    const float* lpb  = (const float*)d_in[5];
    const float* lgw  = (const float*)d_in[6];
    const float* lgb  = (const float*)d_in[7];
    const float* rpw  = (const float*)d_in[8];
    const float* rpb  = (const float*)d_in[9];
    const float* rgw  = (const float*)d_in[10];
    const float* rgb  = (const float*)d_in[11];
    const float* onw  = (const float*)d_in[12];
    const float* onb  = (const float*)d_in[13];
    const float* opw  = (const float*)d_in[14];
    const float* opb  = (const float*)d_in[15];
    const float* ogw  = (const float*)d_in[16];
    const float* ogb  = (const float*)d_in[17];
    float* out = (float*)d_out;

    const int smem1 = K1_ST + 64*129*4 + 1024;   // ~82 KB
    const int smem2 = 3*K2_BUF + 256;            // ~72 KB
    const int smem3 = 65536 + 1024;              // 64 KB
    cudaFuncSetAttribute(k1_tc,  cudaFuncAttributeMaxDynamicSharedMemorySize, smem1);
    cudaFuncSetAttribute(k2_mma, cudaFuncAttributeMaxDynamicSharedMemorySize, smem2);
    cudaFuncSetAttribute(k3_tc,  cudaFuncAttributeMaxDynamicSharedMemorySize, smem3);

    k0_prep<<<dim3(64, 6), 256>>>(lpw, lgw, rpw, rgw, ogw, opw);

    k1_tc<<<NN/64, 256, smem1>>>(pair, mask, nw, nb, lpb, lgb, rpb, rgb, ogb);

    dim3 g2(32, 128);   // x = i-tile(4) x j-tile(8): consecutive blocks share the A tile in L2
    k2_mma<<<g2, 256, smem2>>>();

    k3_tc<<<NN/64, 256, smem3>>>(onw, onb, opb, out);
}

// round 15
// speedup vs baseline: 1.4837x; 1.0440x over previous
#include <cuda_runtime.h>
#include <cuda_fp16.h>
#include <cstdint>

#define NDIM 512
#define DDIM 128
#define NN (NDIM*NDIM)

// ---------------- scratch (device globals; no allocation allowed) ----------------
__device__ __align__(256) __half g_lH[(size_t)DDIM*NN];     // left  [d][i][k] fp16
__device__ __align__(256) __half g_rH[(size_t)DDIM*NN];     // right [d][j][k] fp16
__device__ __align__(256) __half g_gate[(size_t)NN*DDIM];   // fp16 gate
__device__ __align__(256) __half g_accT[(size_t)DDIM*NN];   // fp16 [d][i][j]
// plain fp16 weights: 0=lp 1=lg 2=rp 3=rg 4=og 5=op  (row-major [n][k])
__device__ __align__(256) __half g_wh[6*16384];

__device__ __forceinline__ float sigf(float x){ return 1.0f/(1.0f+__expf(-x)); }

__device__ __forceinline__ uint32_t smem_u32(const void* p){
    uint32_t a;
    asm("{ .reg .u64 t; cvta.to.shared.u64 t, %1; cvt.u32.u64 %0, t; }" : "=r"(a) : "l"(p));
    return a;
}

// ---------------- baseline-PTX tensor-core helpers (fp16) ----------------
__device__ __forceinline__ void ldsm4(uint32_t (&r)[4], uint32_t a){
    asm volatile("ldmatrix.sync.aligned.m8n8.x4.shared.b16 {%0,%1,%2,%3}, [%4];"
        : "=r"(r[0]), "=r"(r[1]), "=r"(r[2]), "=r"(r[3]) : "r"(a));
}
__device__ __forceinline__ void ldsm2(uint32_t (&r)[2], uint32_t a){
    asm volatile("ldmatrix.sync.aligned.m8n8.x2.shared.b16 {%0,%1}, [%2];"
        : "=r"(r[0]), "=r"(r[1]) : "r"(a));
}
__device__ __forceinline__ void mma_f16(float (&c)[4], const uint32_t (&a)[4], const uint32_t (&b)[2]){
    asm volatile("mma.sync.aligned.m16n8k16.row.col.f32.f16.f16.f32 "
        "{%0,%1,%2,%3}, {%4,%5,%6,%7}, {%8,%9}, {%0,%1,%2,%3};"
        : "+f"(c[0]), "+f"(c[1]), "+f"(c[2]), "+f"(c[3])
        : "r"(a[0]), "r"(a[1]), "r"(a[2]), "r"(a[3]), "r"(b[0]), "r"(b[1]));
}
#define CP_ASYNC16(dst, src) \
    asm volatile("cp.async.cg.shared.global [%0], [%1], 16;" :: "r"(dst), "l"(src) : "memory")
#define CP_COMMIT() asm volatile("cp.async.commit_group;" ::: "memory")
#define CP_WAIT0()  asm volatile("cp.async.wait_group 0;" ::: "memory")
#define CP_WAIT1()  asm volatile("cp.async.wait_group 1;" ::: "memory")
#define CP_WAIT2()  asm volatile("cp.async.wait_group 2;" ::: "memory")

// ---------------- Kernel 0: weights -> fp16 ----------------
__global__ void k0_prep(const float* __restrict__ lpw, const float* __restrict__ lgw,
                        const float* __restrict__ rpw, const float* __restrict__ rgw,
                        const float* __restrict__ ogw, const float* __restrict__ opw)
{
    const float* srcs[6] = {lpw, lgw, rpw, rgw, ogw, opw};
    int m = blockIdx.y;
    int idx = blockIdx.x * 256 + threadIdx.x;
    g_wh[m*16384 + idx] = __float2half_rn(srcs[m][idx]);
}

// ================= Kernel 1: LN + 5 gated projections (64-row tiles, 2 CTA/SM) ==========
// smem: A fp16 [0,16K) 64x256B ; WP [16K,48K) ; WG [48K,80K)
//       st uint32 (33KB) overlays [16K,49.3K) after GEMMs complete
__global__ void __launch_bounds__(256, 2)
k1_tc(const float* __restrict__ pair, const float* __restrict__ mask,
      const float* __restrict__ nw,  const float* __restrict__ nb,
      const float* __restrict__ lpb, const float* __restrict__ lgb,
      const float* __restrict__ rpb, const float* __restrict__ rgb,
      const float* __restrict__ ogb)
{
    extern __shared__ char smraw[];
    char* smb = (char*)(((uintptr_t)smraw + 1023) & ~(uintptr_t)1023);
    const uint32_t sb = smem_u32(smb);
    uint32_t* st = (uint32_t*)(smb + 16384);
    __shared__ float mask_s[64];
    __shared__ float pb_s[128], gb_s[128];

    const int tid  = threadIdx.x;
    const int lane = tid & 31;
    const int wid  = tid >> 5;
    const int wm   = wid & 1;
    const int wn   = wid >> 1;
    const int row0 = blockIdx.x * 64;
    const int i_idx = row0 >> 9;
    const int k0    = row0 & 511;

    // load one 32KB weight into the slot at smem offset `soff`
    auto loadW = [&](const __half* src, uint32_t soff){
        #pragma unroll
        for (int t = 0; t < 8; t++){
            int idx = tid + (t << 8);          // 0..2047 16B chunks
            int d = idx >> 4;
            int c = idx & 15;
            uint32_t off = (uint32_t)(d*256 + (((c ^ (d & 7)) << 4)));
            CP_ASYNC16(sb + soff + off, (const char*)src + (idx << 4));
        }
        CP_COMMIT();
    };

    // prefetch pass-A weight pair (lp,lg) — overlapped with LN below
    loadW(g_wh,           16384u);
    loadW(g_wh + 16384,   49152u);
    if (tid < 64) mask_s[tid] = mask[row0 + tid];

    // ---- LN from registers (4 threads per row), write fp16 A ----
    {
        int row = tid >> 2, q = tid & 3;
        const float4* pr = (const float4*)(pair + (size_t)(row0 + row)*128 + q*32);
        float v[32];
        float s = 0.f, ss = 0.f;
        #pragma unroll
        for (int t = 0; t < 8; t++){
            float4 x = pr[t];
            v[t*4+0] = x.x; v[t*4+1] = x.y; v[t*4+2] = x.z; v[t*4+3] = x.w;
            s  += x.x + x.y + x.z + x.w;
            ss += x.x*x.x + x.y*x.y + x.z*x.z + x.w*x.w;
        }
        s  += __shfl_xor_sync(0xFFFFFFFFu, s, 1);
        ss += __shfl_xor_sync(0xFFFFFFFFu, ss, 1);
        s  += __shfl_xor_sync(0xFFFFFFFFu, s, 2);
        ss += __shfl_xor_sync(0xFFFFFFFFu, ss, 2);
        float m  = s * (1.f/128.f);
        float vv = fmaxf(ss * (1.f/128.f) - m*m, 0.f);
        float iv = rsqrtf(vv + 1e-5f);
        #pragma unroll
        for (int cc = 0; cc < 4; cc++){
            int c = q*4 + cc;
            int e = q*32 + cc*8;
            uint4 pv;
            unsigned short* pp = (unsigned short*)&pv;
            #pragma unroll
            for (int t = 0; t < 8; t++){
                float y = (v[cc*8 + t] - m)*iv*nw[e + t] + nb[e + t];
                pp[t] = __half_as_ushort(__float2half_rn(y));
            }
            uint32_t off = (uint32_t)(row*256 + (((c ^ (row & 7)) << 4)));
            *(uint4*)(smb + off) = pv;
        }
    }

    // fused dual GEMM: A [0,16K), WP [16K,48K), WG [48K,80K). A-frags reused.
    auto gemmPG = [&](float (&accp)[2][4][4], float (&accg)[2][4][4]){
        #pragma unroll
        for (int a = 0; a < 2; a++)
            #pragma unroll
            for (int b = 0; b < 4; b++)
                #pragma unroll
                for (int q = 0; q < 4; q++){ accp[a][b][q] = 0.f; accg[a][b][q] = 0.f; }
        #pragma unroll 1
        for (int fkk = 0; fkk < 8; fkk++){
            uint32_t ap[2][4];
            #pragma unroll
            for (int mt = 0; mt < 2; mt++){
                int r = wm*32 + mt*16 + (lane & 15);
                int c = fkk*2 + (lane >> 4);
                ldsm4(ap[mt], sb + (uint32_t)(r*256 + (((c ^ (r & 7)) << 4))));
            }
            uint32_t bpP[4][2], bpG[4][2];
            #pragma unroll
            for (int nt = 0; nt < 4; nt++){
                int l = lane & 15;
                int n = wn*32 + nt*8 + (l & 7);
                int c = fkk*2 + (l >> 3);
                uint32_t off = (uint32_t)(n*256 + (((c ^ (n & 7)) << 4)));
                ldsm2(bpP[nt], sb + 16384 + off);
                ldsm2(bpG[nt], sb + 49152 + off);
            }
            #pragma unroll
            for (int mt = 0; mt < 2; mt++)
                #pragma unroll
                for (int nt = 0; nt < 4; nt++){
                    mma_f16(accp[mt][nt], ap[mt], bpP[nt]);
                    mma_f16(accg[mt][nt], ap[mt], bpG[nt]);
                }
        }
    };

    // single GEMM against WP slot
    auto gemmW = [&](float (&acc)[2][4][4]){
        #pragma unroll
        for (int a = 0; a < 2; a++)
            #pragma unroll
            for (int b = 0; b < 4; b++)
                #pragma unroll
                for (int q = 0; q < 4; q++) acc[a][b][q] = 0.f;
        #pragma unroll 1
        for (int fkk = 0; fkk < 8; fkk++){
            uint32_t ap[2][4];
            #pragma unroll
            for (int mt = 0; mt < 2; mt++){
                int r = wm*32 + mt*16 + (lane & 15);
                int c = fkk*2 + (lane >> 4);
                ldsm4(ap[mt], sb + (uint32_t)(r*256 + (((c ^ (r & 7)) << 4))));
            }
            uint32_t bp[4][2];
            #pragma unroll
            for (int nt = 0; nt < 4; nt++){
                int l = lane & 15;
                int n = wn*32 + nt*8 + (l & 7);
                int c = fkk*2 + (l >> 3);
                ldsm2(bp[nt], sb + 16384 + (uint32_t)(n*256 + (((c ^ (n & 7)) << 4))));
            }
            #pragma unroll
            for (int mt = 0; mt < 2; mt++)
                #pragma unroll
                for (int nt = 0; nt < 4; nt++)
                    mma_f16(acc[mt][nt], ap[mt], bp[nt]);
        }
    };

    // ---- passes A (left) / B (right): fused value+gate ----
    #pragma unroll 1
    for (int pa = 0; pa < 2; pa++){
        if (pa){
            loadW(g_wh + 2*16384, 16384u);
            loadW(g_wh + 3*16384, 49152u);
        }
        if (tid < 128){
            pb_s[tid] = pa ? rpb[tid] : lpb[tid];
            gb_s[tid] = pa ? rgb[tid] : lgb[tid];
        }
        CP_WAIT0();
        __syncthreads();
        float accp[2][4][4], accg[2][4][4];
        gemmPG(accp, accg);
        __syncthreads();   // W reads done; st may overwrite

        #pragma unroll
        for (int mt = 0; mt < 2; mt++)
            #pragma unroll
            for (int nt = 0; nt < 4; nt++)
                #pragma unroll
                for (int q = 0; q < 4; q++){
                    int m = wm*32 + mt*16 + (lane >> 2) + ((q >> 1) << 3);
                    int n = wn*32 + nt*8 + ((lane & 3) << 1) + (q & 1);
                    float x = accp[mt][nt][q] + pb_s[n];
                    float g = accg[mt][nt][q] + gb_s[n];
                    float y = x * sigf(g) * mask_s[m];
                    st[m*129 + n] = (uint32_t)__half_as_ushort(__float2half_rn(y));
                }
        __syncthreads();

        // transpose write: fp16 [d][i][k]
        {
            __half* gH = pa ? g_rH : g_lH;
            int dd = tid >> 1, half = tid & 1;
            uint4 o[4];
            unsigned short* op = (unsigned short*)o;
            #pragma unroll
            for (int kk = 0; kk < 32; kk++)
                op[kk] = (unsigned short)st[(half*32 + kk)*129 + dd];
            __half* dst = gH + ((size_t)dd*NDIM + i_idx)*NDIM + k0 + half*32;
            #pragma unroll
            for (int q = 0; q < 4; q++)
                *(uint4*)(dst + q*8) = o[q];
        }
        __syncthreads();
    }

    // ---- pass C: output gate (direct fp16 stores) ----
    loadW(g_wh + 4*16384, 16384u);
    if (tid < 128) pb_s[tid] = ogb[tid];
    CP_WAIT0();
    __syncthreads();
    {
        float acc[2][4][4];
        gemmW(acc);
        #pragma unroll
        for (int mt = 0; mt < 2; mt++)
            #pragma unroll
            for (int nt = 0; nt < 4; nt++)
                #pragma unroll
                for (int qq = 0; qq < 2; qq++){
                    int m = wm*32 + mt*16 + (lane >> 2) + qq*8;
                    int n = wn*32 + nt*8 + ((lane & 3) << 1);
                    float gx = sigf(acc[mt][nt][qq*2+0] + pb_s[n+0]);
                    float gy = sigf(acc[mt][nt][qq*2+1] + pb_s[n+1]);
                    *(__half2*)&g_gate[(size_t)(row0 + m)*DDIM + n] = __floats2half2_rn(gx, gy);
                }
    }
}

// ================= Kernel 2: einsum, 128x64 tiles, K64 chunks, 3-stage =========
// per buffer (24KB): A fp16 [0,16K) 128x128B ; B fp16 [16K,24K) 64x128B
#define K2_BUF 24576

__global__ void __launch_bounds__(256, 3)
k2_mma()
{
    extern __shared__ char smraw[];
    char* smb = (char*)(((uintptr_t)smraw + 127) & ~(uintptr_t)127);
    const uint32_t sb = smem_u32(smb);

    const int tid  = threadIdx.x;
    const int lane = tid & 31;
    const int wid  = tid >> 5;
    const int d    = blockIdx.y;
    const int i0   = (blockIdx.x >> 3) * 128;
    const int j0   = (blockIdx.x & 7) * 64;
    const int wm   = wid & 3;          // 4 m-groups of 32 rows
    const int wn   = wid >> 2;         // 2 n-groups of 32 cols

    auto load_chunk = [&](int kc, int b){
        #pragma unroll
        for (int t = 0; t < 6; t++){
            int idx = tid + (t << 8);          // 0..1535 16B chunks
            const __half* src;
            int rb, r;
            uint32_t roff;
            if (idx < 1024){
                src = g_lH; rb = i0; r = idx >> 3; roff = 0u;
            } else {
                int x = idx - 1024;
                src = g_rH; rb = j0; r = x >> 3; roff = 16384u;
            }
            int c = idx & 7;
            const void* gp = src + ((size_t)d*NDIM + rb + r)*NDIM + kc + (c << 3);
            uint32_t dst = sb + b*K2_BUF + roff + (r << 7) + (((c ^ (r & 7)) << 4));
            CP_ASYNC16(dst, gp);
        }
        CP_COMMIT();
    };

    float acc[2][4][4];
    #pragma unroll
    for (int a = 0; a < 2; a++)
        #pragma unroll
        for (int b = 0; b < 4; b++)
            #pragma unroll
            for (int q = 0; q < 4; q++) acc[a][b][q] = 0.f;

    load_chunk(0, 0);
    load_chunk(64, 1);
    load_chunk(128, 2);

    int cs = 0;
    #pragma unroll 1
    for (int t = 0; t < 8; t++){
        if (t <= 5)      CP_WAIT2();
        else if (t == 6) CP_WAIT1();
        else             CP_WAIT0();
        __syncthreads();

        const uint32_t base = sb + cs*K2_BUF;
        #pragma unroll
        for (int fkk = 0; fkk < 4; fkk++){
            uint32_t ap[2][4], bp[4][2];
            #pragma unroll
            for (int mt = 0; mt < 2; mt++){
                int m = wm*32 + mt*16 + (lane & 15);
                int c = fkk*2 + (lane >> 4);
                ldsm4(ap[mt], base + (uint32_t)((m << 7) + (((c ^ (m & 7)) << 4))));
            }
            #pragma unroll
            for (int nt = 0; nt < 4; nt++){
                int l = lane & 15;
                int n = wn*32 + nt*8 + (l & 7);
                int c = fkk*2 + (l >> 3);
                ldsm2(bp[nt], base + 16384 + (uint32_t)((n << 7) + (((c ^ (n & 7)) << 4))));
            }
            #pragma unroll
            for (int mt = 0; mt < 2; mt++)
                #pragma unroll
                for (int nt = 0; nt < 4; nt++)
                    mma_f16(acc[mt][nt], ap[mt], bp[nt]);
        }
        __syncthreads();
        if (t + 3 < 8) load_chunk((t + 3)*64, cs);   // cs buffer just freed
        cs = (cs == 2) ? 0 : cs + 1;
    }

    // epilogue: write accT fp16 (half2 along j)
    #pragma unroll
    for (int mt = 0; mt < 2; mt++){
        int r0 = i0 + wm*32 + mt*16 + (lane >> 2);
        #pragma unroll
        for (int nt = 0; nt < 4; nt++){
            int c0 = j0 + wn*32 + nt*8 + (lane & 3)*2;
            __half* p0 = &g_accT[((size_t)d*NDIM + r0)*NDIM + c0];
            __half* p1 = &g_accT[((size_t)d*NDIM + r0 + 8)*NDIM + c0];
            *(__half2*)p0 = __floats2half2_rn(acc[mt][nt][0], acc[mt][nt][1]);
            *(__half2*)p1 = __floats2half2_rn(acc[mt][nt][2], acc[mt][nt][3]);
        }
    }
}

// ================= Kernel 3: LN(accT) @ opw.T + opb, times gate (64-j tiles, 3 CTA/SM) ====
// smem: A fp16 [0,16K) ; W fp16 [16K,48K) ; ts [48K,64K)
#define K3_TS 49152
__global__ void __launch_bounds__(256, 3)
k3_tc(const float* __restrict__ onw, const float* __restrict__ onb,
      const float* __restrict__ opb, float* __restrict__ out)
{
    extern __shared__ char smraw[];
    char* smb = (char*)(((uintptr_t)smraw + 1023) & ~(uintptr_t)1023);
    const uint32_t sb = smem_u32(smb);
    __shared__ float pb_s[128];
    __shared__ float sred[4][64], qred[4][64];
    __shared__ float mean_s[64], inv_s[64];

    const int tid  = threadIdx.x;
    const int lane = tid & 31;
    const int wid  = tid >> 5;
    const int wm   = wid & 1;
    const int wn   = wid >> 1;
    const int i_idx = blockIdx.x >> 3;
    const int j0    = (blockIdx.x & 7) * 64;
    const int row0  = i_idx*NDIM + j0;

    // group 0: accT tile -> ts [48K,64K), fully coalesced
    #pragma unroll
    for (int t = 0; t < 4; t++){
        int idx = tid + (t << 8);          // 0..1023 16B chunks
        int d = idx >> 3;
        int c = idx & 7;
        CP_ASYNC16(sb + K3_TS + (uint32_t)(d*128 + c*16),
                   (const char*)(g_accT + (size_t)d*NN + row0) + (c << 4));
    }
    CP_COMMIT();

    // group 1: op weight prefetch -> [16K,48K)
    #pragma unroll
    for (int t = 0; t < 8; t++){
        int idx = tid + (t << 8);
        int d = idx >> 4;
        int c = idx & 15;
        uint32_t off = (uint32_t)(d*256 + (((c ^ (d & 7)) << 4)));
        CP_ASYNC16(sb + 16384 + off, (const char*)(g_wh + 5*16384) + (idx << 4));
    }
    CP_COMMIT();
    if (tid < 128) pb_s[tid] = opb[tid];

    CP_WAIT1();          // ts complete; W may still be in flight
    __syncthreads();

    // ---- LN over d per j (no register cache; re-read from smem in pack) ----
    const int jj = tid & 63, qq4 = tid >> 6;
    const __half* tsm = (const __half*)(smb + K3_TS);
    {
        float s = 0.f, ss = 0.f;
        #pragma unroll
        for (int t = 0; t < 32; t++){
            float x = __half2float(tsm[(qq4*32 + t)*64 + jj]);
            s += x; ss += x*x;
        }
        sred[qq4][jj] = s; qred[qq4][jj] = ss;
    }
    __syncthreads();
    if (tid < 64){
        int j = tid;
        float S  = sred[0][j] + sred[1][j] + sred[2][j] + sred[3][j];
        float SS = qred[0][j] + qred[1][j] + qred[2][j] + qred[3][j];
        float m  = S * (1.f/128.f);
        float vv = fmaxf(SS * (1.f/128.f) - m*m, 0.f);
        mean_s[j] = m;
        inv_s[j]  = rsqrtf(vv + 1e-5f);
    }
    __syncthreads();
    // pack phase: read ts via LDS, write fp16 A [0,16K)
    {
        float m = mean_s[jj], iv = inv_s[jj];
        #pragma unroll
        for (int cc = 0; cc < 4; cc++){
            int c = qq4*4 + cc;
            int e = qq4*32 + cc*8;
            uint4 pv;
            unsigned short* pp = (unsigned short*)&pv;
            #pragma unroll
            for (int t = 0; t < 8; t++){
                float x = __half2float(tsm[(e + t)*64 + jj]);
                float y = (x - m)*iv*onw[e + t] + onb[e + t];
                pp[t] = __half_as_ushort(__float2half_rn(y));
            }
            uint32_t off = (uint32_t)(jj*256 + (((c ^ (jj & 7)) << 4)));
            *(uint4*)(smb + off) = pv;
        }
    }
    CP_WAIT0();
    __syncthreads();

    float acc[2][4][4];
    #pragma unroll
    for (int a = 0; a < 2; a++)
        #pragma unroll
        for (int b = 0; b < 4; b++)
            #pragma unroll
            for (int q = 0; q < 4; q++) acc[a][b][q] = 0.f;

    #pragma unroll 1
    for (int fkk = 0; fkk < 8; fkk++){
        uint32_t ap[2][4];
        #pragma unroll
        for (int mt = 0; mt < 2; mt++){
            int r = wm*32 + mt*16 + (lane & 15);
            int c = fkk*2 + (lane >> 4);
            ldsm4(ap[mt], sb + (uint32_t)(r*256 + (((c ^ (r & 7)) << 4))));
        }
        uint32_t bp[4][2];
        #pragma unroll
        for (int nt = 0; nt < 4; nt++){
            int l = lane & 15;
            int n = wn*32 + nt*8 + (l & 7);
            int c = fkk*2 + (l >> 3);
            ldsm2(bp[nt], sb + 16384 + (uint32_t)(n*256 + (((c ^ (n & 7)) << 4))));
        }
        #pragma unroll
        for (int mt = 0; mt < 2; mt++)
            #pragma unroll
            for (int nt = 0; nt < 4; nt++)
                mma_f16(acc[mt][nt], ap[mt], bp[nt]);
    }

    // epilogue: (acc + opb) * gate(fp16), direct global loads/stores
    #pragma unroll
    for (int mt = 0; mt < 2; mt++)
        #pragma unroll
        for (int nt = 0; nt < 4; nt++)
            #pragma unroll
            for (int qq = 0; qq < 2; qq++){
                int j = wm*32 + mt*16 + (lane >> 2) + qq*8;
                int n = wn*32 + nt*8 + ((lane & 3) << 1);
                size_t base = (size_t)(row0 + j)*DDIM + n;
                float2 g2 = __half22float2(*(const __half2*)&g_gate[base]);
                float2 o;
                o.x = (acc[mt][nt][qq*2+0] + pb_s[n+0]) * g2.x;
                o.y = (acc[mt][nt][qq*2+1] + pb_s[n+1]) * g2.y;
                *(float2*)&out[base] = o;
            }
}

extern "C" void kernel_launch(void* const* d_in, const int* in_sizes, int n_in,
                              void* d_out, int out_size)
{
    const float* pair = (const float*)d_in[0];
    const float* mask = (const float*)d_in[1];
    const float* nw   = (const float*)d_in[2];
    const float* nb   = (const float*)d_in[3];
    const float* lpw  = (const float*)d_in[4];
    const float* lpb  = (const float*)d_in[5];
    const float* lgw  = (const float*)d_in[6];
    const float* lgb  = (const float*)d_in[7];
    const float* rpw  = (const float*)d_in[8];
    const float* rpb  = (const float*)d_in[9];
    const float* rgw  = (const float*)d_in[10];
    const float* rgb  = (const float*)d_in[11];
    const float* onw  = (const float*)d_in[12];
    const float* onb  = (const float*)d_in[13];
    const float* opw  = (const float*)d_in[14];
    const float* opb  = (const float*)d_in[15];
    const float* ogw  = (const float*)d_in[16];
    const float* ogb  = (const float*)d_in[17];
    float* out = (float*)d_out;

    const int smem1 = 81920 + 1024;              // A 16K + W 64K + pad
    const int smem2 = 3*K2_BUF + 256;            // ~72 KB
    const int smem3 = 65536 + 1024;              // 64 KB + pad
    cudaFuncSetAttribute(k1_tc,  cudaFuncAttributeMaxDynamicSharedMemorySize, smem1);
    cudaFuncSetAttribute(k2_mma, cudaFuncAttributeMaxDynamicSharedMemorySize, smem2);
    cudaFuncSetAttribute(k3_tc,  cudaFuncAttributeMaxDynamicSharedMemorySize, smem3);

    k0_prep<<<dim3(64, 6), 256>>>(lpw, lgw, rpw, rgw, ogw, opw);

    k1_tc<<<NN/64, 256, smem1>>>(pair, mask, nw, nb, lpb, lgb, rpb, rgb, ogb);

    dim3 g2(32, 128);   // x = i-tile(4) x j-tile(8): consecutive blocks share the A tile in L2
    k2_mma<<<g2, 256, smem2>>>();

    k3_tc<<<NN/64, 256, smem3>>>(onw, onb, opb, out);
}